// round 1
// baseline (speedup 1.0000x reference)
#include <cuda_runtime.h>

// TensorProductUniform3x1d:
//   B=100000, NSEG=4, U=128, NPATH=20
//   out[b, i2, :] += c[p] * x0[b, i0[p], :] * x1[b, i1[p], :]
//
// Strategy: collapse the 20 runtime paths into a dense W[4][4][4] tensor
// (built by a tiny pre-kernel), then the main kernel is a static, fully
// unrolled contraction with perfectly coalesced float4 streaming.

#define NSEG 4
#define U 128
#define NPATH 20

// Scratch for the collapsed coefficient tensor (no cudaMalloc allowed).
__device__ float g_W[NSEG * NSEG * NSEG];

__global__ void build_W_kernel(const float* __restrict__ coeff,
                               const int* __restrict__ idx) {
    int t = threadIdx.x;            // 64 threads, one per (i2,i0,i1)
    if (t >= NSEG * NSEG * NSEG) return;
    int i2 = t >> 4;
    int i0 = (t >> 2) & 3;
    int i1 = t & 3;
    float w = 0.0f;
    #pragma unroll
    for (int p = 0; p < NPATH; p++) {
        int p0 = idx[3 * p + 0];
        int p1 = idx[3 * p + 1];
        int p2 = idx[3 * p + 2];
        if (p0 == i0 && p1 == i1 && p2 == i2) w += coeff[p];
    }
    g_W[t] = w;
}

// One warp per batch row. Lane l owns float4 column l of each 128-float
// segment: loads x0/x1 seg s at [row*128 + s*32 + l] (float4 units).
// Warp-level access = 32 lanes * 16B = 512B contiguous per segment.
__global__ __launch_bounds__(256)
void tp_uniform_kernel(const float4* __restrict__ x0,
                       const float4* __restrict__ x1,
                       float4* __restrict__ out,
                       int nrows) {
    __shared__ float sW[NSEG * NSEG * NSEG];
    if (threadIdx.x < NSEG * NSEG * NSEG) sW[threadIdx.x] = g_W[threadIdx.x];
    __syncthreads();

    int gid  = blockIdx.x * blockDim.x + threadIdx.x;
    int row  = gid >> 5;
    int lane = gid & 31;
    if (row >= nrows) return;

    size_t base = (size_t)row * (NSEG * U / 4) + lane;  // float4 units

    float4 a[NSEG], b[NSEG];
    #pragma unroll
    for (int s = 0; s < NSEG; s++) {
        a[s] = __ldg(&x0[base + s * (U / 4)]);
        b[s] = __ldg(&x1[base + s * (U / 4)]);
    }

    // out[i2] = sum_{i0} a[i0] * ( sum_{i1} W[i2][i0][i1] * b[i1] )
    #pragma unroll
    for (int i2 = 0; i2 < NSEG; i2++) {
        float4 acc = make_float4(0.f, 0.f, 0.f, 0.f);
        #pragma unroll
        for (int i0 = 0; i0 < NSEG; i0++) {
            float4 t = make_float4(0.f, 0.f, 0.f, 0.f);
            #pragma unroll
            for (int i1 = 0; i1 < NSEG; i1++) {
                float w = sW[(i2 * NSEG + i0) * NSEG + i1];
                t.x = fmaf(w, b[i1].x, t.x);
                t.y = fmaf(w, b[i1].y, t.y);
                t.z = fmaf(w, b[i1].z, t.z);
                t.w = fmaf(w, b[i1].w, t.w);
            }
            acc.x = fmaf(a[i0].x, t.x, acc.x);
            acc.y = fmaf(a[i0].y, t.y, acc.y);
            acc.z = fmaf(a[i0].z, t.z, acc.z);
            acc.w = fmaf(a[i0].w, t.w, acc.w);
        }
        out[base + i2 * (U / 4)] = acc;
    }
}

extern "C" void kernel_launch(void* const* d_in, const int* in_sizes, int n_in,
                              void* d_out, int out_size) {
    const float4* x0    = (const float4*)d_in[0];
    const float4* x1    = (const float4*)d_in[1];
    const float*  coeff = (const float*)d_in[2];
    const int*    idx   = (const int*)d_in[3];
    float4*       out   = (float4*)d_out;

    int nrows = in_sizes[0] / (NSEG * U);   // 100000

    build_W_kernel<<<1, 64>>>(coeff, idx);

    int total_threads = nrows * 32;         // one warp per row
    int block = 256;
    int grid  = (total_threads + block - 1) / block;
    tp_uniform_kernel<<<grid, block>>>(x0, x1, out, nrows);
}

// round 2
// speedup vs baseline: 1.0007x; 1.0007x over previous
#include <cuda_runtime.h>

// TensorProductUniform3x1d:
//   B=100000, NSEG=4, U=128, NPATH=20
//   out[b, i2, :] += c[p] * x0[b, i0[p], :] * x1[b, i1[p], :]
//
// Single fused kernel: every block builds the collapsed 4x4x4 coefficient
// tensor W in shared memory from (path_indices, path_coefficients) — the
// index/coeff arrays are tiny and L2-resident, so redundant per-block
// construction is free — then performs the static, fully unrolled
// contraction with perfectly coalesced float4 streaming.

#define NSEG 4
#define U 128
#define NPATH 20

// One warp per batch row. Lane l owns float4 column l of each 128-float
// segment. Warp-level access = 32 lanes * 16B = 512B contiguous per segment.
__global__ __launch_bounds__(256, 4)
void tp_uniform_fused_kernel(const float4* __restrict__ x0,
                             const float4* __restrict__ x1,
                             const float*  __restrict__ coeff,
                             const int*    __restrict__ idx,
                             float4* __restrict__ out,
                             int nrows) {
    __shared__ float sW[NSEG * NSEG * NSEG];

    // Build W[i2][i0][i1] = sum_p coeff[p] * [idx[p]==(i0,i1,i2)]
    int t = threadIdx.x;
    if (t < NSEG * NSEG * NSEG) {
        int i2 = t >> 4;
        int i0 = (t >> 2) & 3;
        int i1 = t & 3;
        float w = 0.0f;
        #pragma unroll
        for (int p = 0; p < NPATH; p++) {
            int p0 = __ldg(&idx[3 * p + 0]);
            int p1 = __ldg(&idx[3 * p + 1]);
            int p2 = __ldg(&idx[3 * p + 2]);
            if (p0 == i0 && p1 == i1 && p2 == i2) w += __ldg(&coeff[p]);
        }
        sW[t] = w;
    }
    __syncthreads();

    int gid  = blockIdx.x * blockDim.x + threadIdx.x;
    int row  = gid >> 5;
    int lane = gid & 31;
    if (row >= nrows) return;

    size_t base = (size_t)row * (NSEG * U / 4) + lane;  // float4 units

    float4 a[NSEG], b[NSEG];
    #pragma unroll
    for (int s = 0; s < NSEG; s++) {
        a[s] = __ldg(&x0[base + s * (U / 4)]);
        b[s] = __ldg(&x1[base + s * (U / 4)]);
    }

    // out[i2] = sum_{i0} a[i0] * ( sum_{i1} W[i2][i0][i1] * b[i1] )
    #pragma unroll
    for (int i2 = 0; i2 < NSEG; i2++) {
        float4 acc = make_float4(0.f, 0.f, 0.f, 0.f);
        #pragma unroll
        for (int i0 = 0; i0 < NSEG; i0++) {
            float4 tt = make_float4(0.f, 0.f, 0.f, 0.f);
            #pragma unroll
            for (int i1 = 0; i1 < NSEG; i1++) {
                float w = sW[(i2 * NSEG + i0) * NSEG + i1];
                tt.x = fmaf(w, b[i1].x, tt.x);
                tt.y = fmaf(w, b[i1].y, tt.y);
                tt.z = fmaf(w, b[i1].z, tt.z);
                tt.w = fmaf(w, b[i1].w, tt.w);
            }
            acc.x = fmaf(a[i0].x, tt.x, acc.x);
            acc.y = fmaf(a[i0].y, tt.y, acc.y);
            acc.z = fmaf(a[i0].z, tt.z, acc.z);
            acc.w = fmaf(a[i0].w, tt.w, acc.w);
        }
        out[base + i2 * (U / 4)] = acc;
    }
}

extern "C" void kernel_launch(void* const* d_in, const int* in_sizes, int n_in,
                              void* d_out, int out_size) {
    const float4* x0    = (const float4*)d_in[0];
    const float4* x1    = (const float4*)d_in[1];
    const float*  coeff = (const float*)d_in[2];
    const int*    idx   = (const int*)d_in[3];
    float4*       out   = (float4*)d_out;

    int nrows = in_sizes[0] / (NSEG * U);   // 100000

    int total_threads = nrows * 32;         // one warp per row
    int block = 256;
    int grid  = (total_threads + block - 1) / block;
    tp_uniform_fused_kernel<<<grid, block>>>(x0, x1, coeff, idx, out, nrows);
}

// round 3
// speedup vs baseline: 1.0052x; 1.0045x over previous
#include <cuda_runtime.h>

// TensorProductUniform3x1d:
//   B=100000, NSEG=4, U=128, NPATH=20
//   out[b, i2, :] += c[p] * x0[b, i0[p], :] * x1[b, i1[p], :]
//
// Single fused kernel: every block builds the collapsed 4x4x4 coefficient
// tensor W in shared memory (idx/coeff are tiny and L2-resident), then does
// the static fully-unrolled contraction as a pure stream.
//
// R3: streaming (.cs evict-first) loads and stores — data has zero reuse,
// so keep it out of L2's way; front-batched LDGs for max MLP.

#define NSEG 4
#define U 128
#define NPATH 20

__global__ __launch_bounds__(256, 4)
void tp_uniform_fused_kernel(const float4* __restrict__ x0,
                             const float4* __restrict__ x1,
                             const float*  __restrict__ coeff,
                             const int*    __restrict__ idx,
                             float4* __restrict__ out,
                             int nrows) {
    __shared__ float sW[NSEG * NSEG * NSEG];

    // Build W[i2][i0][i1] = sum_p coeff[p] * [idx[p]==(i0,i1,i2)]
    int t = threadIdx.x;
    if (t < NSEG * NSEG * NSEG) {
        int i2 = t >> 4;
        int i0 = (t >> 2) & 3;
        int i1 = t & 3;
        float w = 0.0f;
        #pragma unroll
        for (int p = 0; p < NPATH; p++) {
            int p0 = __ldg(&idx[3 * p + 0]);
            int p1 = __ldg(&idx[3 * p + 1]);
            int p2 = __ldg(&idx[3 * p + 2]);
            if (p0 == i0 && p1 == i1 && p2 == i2) w += __ldg(&coeff[p]);
        }
        sW[t] = w;
    }
    __syncthreads();

    int gid  = blockIdx.x * blockDim.x + threadIdx.x;
    int row  = gid >> 5;
    int lane = gid & 31;
    if (row >= nrows) return;

    size_t base = (size_t)row * (NSEG * U / 4) + lane;  // float4 units

    // Front-batch all 8 streaming loads (evict-first: zero reuse).
    float4 a[NSEG], b[NSEG];
    #pragma unroll
    for (int s = 0; s < NSEG; s++) a[s] = __ldcs(&x0[base + s * (U / 4)]);
    #pragma unroll
    for (int s = 0; s < NSEG; s++) b[s] = __ldcs(&x1[base + s * (U / 4)]);

    // out[i2] = sum_{i0} a[i0] * ( sum_{i1} W[i2][i0][i1] * b[i1] )
    #pragma unroll
    for (int i2 = 0; i2 < NSEG; i2++) {
        float4 acc = make_float4(0.f, 0.f, 0.f, 0.f);
        #pragma unroll
        for (int i0 = 0; i0 < NSEG; i0++) {
            float4 tt = make_float4(0.f, 0.f, 0.f, 0.f);
            #pragma unroll
            for (int i1 = 0; i1 < NSEG; i1++) {
                float w = sW[(i2 * NSEG + i0) * NSEG + i1];
                tt.x = fmaf(w, b[i1].x, tt.x);
                tt.y = fmaf(w, b[i1].y, tt.y);
                tt.z = fmaf(w, b[i1].z, tt.z);
                tt.w = fmaf(w, b[i1].w, tt.w);
            }
            acc.x = fmaf(a[i0].x, tt.x, acc.x);
            acc.y = fmaf(a[i0].y, tt.y, acc.y);
            acc.z = fmaf(a[i0].z, tt.z, acc.z);
            acc.w = fmaf(a[i0].w, tt.w, acc.w);
        }
        __stcs(&out[base + i2 * (U / 4)], acc);
    }
}

extern "C" void kernel_launch(void* const* d_in, const int* in_sizes, int n_in,
                              void* d_out, int out_size) {
    const float4* x0    = (const float4*)d_in[0];
    const float4* x1    = (const float4*)d_in[1];
    const float*  coeff = (const float*)d_in[2];
    const int*    idx   = (const int*)d_in[3];
    float4*       out   = (float4*)d_out;

    int nrows = in_sizes[0] / (NSEG * U);   // 100000

    int total_threads = nrows * 32;         // one warp per row
    int block = 256;
    int grid  = (total_threads + block - 1) / block;
    tp_uniform_fused_kernel<<<grid, block>>>(x0, x1, coeff, idx, out, nrows);
}